// round 13
// baseline (speedup 1.0000x reference)
#include <cuda_runtime.h>
#include <cstdint>

#define L     8192
#define F     9
#define HALF  4096
#define NT    512
#define CH    8        // rows per thread within the half
#define NW    16       // warps per CTA
#define PLH   4608     // padded half length: HALF + HALF/8

__device__ __forceinline__ int pidx(int t) { return t + (t >> 3); }
__device__ __forceinline__ float clip01(float x) { return fminf(fmaxf(x, 0.0f), 0.9999f); }
__device__ __forceinline__ float sel4(int rw, float a, float b, float c, float d) {
    float r = a;
    if (rw == 1) r = b;
    if (rw == 2) r = c;
    if (rw == 3) r = d;
    return r;
}

// In-place inclusive PREFIX scan of arr[0..n-1] by one warp (3 elems/lane).
__device__ __forceinline__ void warp_prefix(float* arr, int n) {
    int lane = threadIdx.x & 31;
    int j = 3 * lane;
    float a0 = (j     < n) ? arr[j]     : 0.0f;
    float a1 = (j + 1 < n) ? arr[j + 1] : 0.0f;
    float a2 = (j + 2 < n) ? arr[j + 2] : 0.0f;
    float p1 = a0 + a1, p2 = p1 + a2;
    float x = p2, tot = p2;
#pragma unroll
    for (int d = 1; d < 32; d <<= 1) {
        float y = __shfl_up_sync(0xFFFFFFFFu, x, d);
        if (lane >= d) x += y;
    }
    float off = x - tot;
    __syncwarp();
    if (j     < n) arr[j]     = off + a0;
    if (j + 1 < n) arr[j + 1] = off + p1;
    if (j + 2 < n) arr[j + 2] = off + p2;
    __syncwarp();
}

// In-place inclusive SUFFIX scan of arr[0..n-1] by one warp.
__device__ __forceinline__ void warp_suffix(float* arr, int n) {
    int lane = threadIdx.x & 31;
    int j = 3 * lane;   // reversed positions n-1-j, n-2-j, n-3-j
    float a0 = (j     < n) ? arr[n - 1 - j] : 0.0f;
    float a1 = (j + 1 < n) ? arr[n - 2 - j] : 0.0f;
    float a2 = (j + 2 < n) ? arr[n - 3 - j] : 0.0f;
    float p1 = a0 + a1, p2 = p1 + a2;
    float x = p2, tot = p2;
#pragma unroll
    for (int d = 1; d < 32; d <<= 1) {
        float y = __shfl_up_sync(0xFFFFFFFFu, x, d);
        if (lane >= d) x += y;
    }
    float off = x - tot;
    __syncwarp();
    if (j     < n) arr[n - 1 - j] = off + a0;
    if (j + 1 < n) arr[n - 2 - j] = off + p1;
    if (j + 2 < n) arr[n - 3 - j] = off + p2;
    __syncwarp();
}

__global__ __launch_bounds__(NT, 2)
void kenneth_kernel(const float* __restrict__ conc,
                    const float* __restrict__ kern,
                    float* __restrict__ out) {
    extern __shared__ float sm[];
    float* sb = sm;                // bcd (padded)
    float* sp = sm + PLH;          // rowsum -> global P (padded)
    float* qf = sm + 2 * PLH;      // Q_f local prefix (padded)
    float* qb = sm + 3 * PLH;      // Q_b local prefix (padded)
    __shared__ float wredo[NW], wredp[NW], wredf[NW], wredb[NW];
    __shared__ float sOther;
    __shared__ float strip_rs[96]; // boundary rowsums / scans
    __shared__ float stripA[96];   // boundary P values
    __shared__ float stripB[80];   // h=1: SSf (suffix of q_f tail) ; h=0: PSb shifted prefix of q_b head

    const int tid  = threadIdx.x;
    const int lane = tid & 31;
    const int wid  = tid >> 5;
    const int row  = blockIdx.x >> 1;
    const int h    = blockIdx.x & 1;
    const float k  = kern[0];
    const float* gin = conc + (size_t)row * (L * F);
    float* outb = out + (size_t)row * (F * L);
    const int hb = h * HALF;

    // ---- S0: flat float4 sum of the OTHER half -> per-warp partials ----
    {
        const float4* o4 = reinterpret_cast<const float4*>(gin + (size_t)(1 - h) * (HALF * F));
        float tot = 0.0f;
#pragma unroll
        for (int g = 0; g < 18; g++) {
            float4 q = o4[g * NT + tid];
            tot += (q.x + q.y) + (q.z + q.w);
        }
#pragma unroll
        for (int d = 16; d >= 1; d >>= 1) tot += __shfl_xor_sync(0xFFFFFFFFu, tot, d);
        if (lane == 0) wredo[wid] = tot;
    }

    // ---- S1: gather own half rows (3 x LDG.128 + sel4), bcd + rowsum -> smem ----
    const int rw = tid & 3;        // (9*tg) mod 4 == tg mod 4 == tid mod 4
#pragma unroll
    for (int ii = 0; ii < CH; ii++) {
        int tl = ii * NT + tid;
        int tg = hb + tl;
        const float4* p4 = reinterpret_cast<const float4*>(gin) + ((9 * tg) >> 2);
        float4 q0 = p4[0], q1 = p4[1], q2 = p4[2];
        float w12[12] = { q0.x, q0.y, q0.z, q0.w,
                          q1.x, q1.y, q1.z, q1.w,
                          q2.x, q2.y, q2.z, q2.w };
        float v[9];
#pragma unroll
        for (int c = 0; c < 9; c++) v[c] = sel4(rw, w12[c], w12[c + 1], w12[c + 2], w12[c + 3]);
        float acc = ((v[1] + v[2]) + (v[3] + v[4]))
                  + ((v[5] + v[6]) + (v[7] + v[8])) + v[0];
        sb[pidx(tl)] = v[0];
        sp[pidx(tl)] = acc;
    }
    __syncthreads();

    // ---- S2: local P scan (chunked ownership) + other-half total reduce ----
    const int base = CH * tid;
    float pv[CH];
    float run = 0.0f;
#pragma unroll
    for (int j = 0; j < CH; j++) { run += sp[pidx(base + j)]; pv[j] = run; }
    float x = run;
#pragma unroll
    for (int d = 1; d < 32; d <<= 1) {
        float y = __shfl_up_sync(0xFFFFFFFFu, x, d);
        if (lane >= d) x += y;
    }
    if (lane == 31) wredp[wid] = x;
    if (wid == 0) {
        float s = (lane < NW) ? wredo[lane] : 0.0f;
#pragma unroll
        for (int d = 16; d >= 1; d >>= 1) s += __shfl_xor_sync(0xFFFFFFFFu, s, d);
        if (lane == 0) sOther = s;
    }
    __syncthreads();
    if (wid == 0) {
        float w = (lane < NW) ? wredp[lane] : 0.0f;
#pragma unroll
        for (int d = 1; d < 32; d <<= 1) {
            float y = __shfl_up_sync(0xFFFFFFFFu, w, d);
            if (lane >= d) w += y;
        }
        if (lane < NW) wredp[lane] = w;
    }
    __syncthreads();

    const float T_other = sOther;
    const float T_own   = wredp[NW - 1];
    const float T0      = h ? T_other : T_own;      // total of FIRST half
    const float Z1      = 1.0f + T_own + T_other;
    const float C2      = Z1 + 1.0f;
    const float invZ1   = 1.0f / Z1;

    {   // write GLOBAL P into sp
        float add0 = 1.0f + (h ? T_other : 0.0f);
        float off = add0 + (x - run) + (wid > 0 ? wredp[wid - 1] : 0.0f);
#pragma unroll
        for (int j = 0; j < CH; j++) sp[pidx(base + j)] = off + pv[j];
    }

    // ---- S3: boundary strip (warp NW-1), from the OTHER half, L2-hot ----
    if (wid == NW - 1) {
        if (h == 1) {
            // first-half tail: rows 4008..4095 rowsums -> suffix -> P
#pragma unroll
            for (int m = 0; m < 3; m++) {
                int j = lane + 32 * m;
                if (j < 88) {
                    const float* p = gin + (size_t)(4008 + j) * 9;
                    float s = p[0];
#pragma unroll
                    for (int c = 1; c < 9; c++) s += p[c];
                    strip_rs[j] = s;
                }
            }
            __syncwarp();
            warp_suffix(strip_rs, 88);               // SufR[i] = sum rows 4008+i..4095
#pragma unroll
            for (int m = 0; m < 3; m++) {
                int i = lane + 32 * m;
                if (i < 89) stripA[i] = 1.0f + T0 - ((i < 88) ? strip_rs[i] : 0.0f); // P_g[4007+i]
            }
            __syncwarp();
            // q_f tail: s = 4021+u -> bcd[s] * P_g[s-14]
#pragma unroll
            for (int m = 0; m < 3; m++) {
                int u = lane + 32 * m;
                if (u < 76)
                    stripB[u] = (u < 75) ? gin[(size_t)(4021 + u) * 9] * stripA[u] : 0.0f;
            }
            __syncwarp();
            warp_suffix(stripB, 76);                 // SSf[u] = sum q_f[4021+u .. 4095]
        } else {
            // second-half head: rows 4096..4183 rowsums -> prefix -> P
#pragma unroll
            for (int m = 0; m < 3; m++) {
                int j = lane + 32 * m;
                if (j < 88) {
                    const float* p = gin + (size_t)(4096 + j) * 9;
                    float s = p[0];
#pragma unroll
                    for (int c = 1; c < 9; c++) s += p[c];
                    strip_rs[j] = s;
                }
            }
            __syncwarp();
            warp_prefix(strip_rs, 88);               // prefix2[j]
#pragma unroll
            for (int m = 0; m < 3; m++) {
                int j = lane + 32 * m;
                if (j < 88) stripA[j] = 1.0f + T0 + strip_rs[j];   // P_g[4096+j]
            }
            __syncwarp();
            // q_b head shifted: stripB[0]=0, stripB[u]=q_b[4096+u-1] for u>=1
#pragma unroll
            for (int m = 0; m < 3; m++) {
                int u = lane + 32 * m;
                if (u < 76)
                    stripB[u] = (u >= 1)
                        ? gin[(size_t)(4096 + u - 1) * 9] * (C2 - stripA[13 + u - 1])
                        : 0.0f;
            }
            __syncwarp();
            warp_prefix(stripB, 76);                 // PSb_s[u] = sum q_b[4096 .. 4096+u-1]
        }
    }
    __syncthreads();

    // ---- S4: q build (with strip halos) + fused dual local scan ----
    {
        float qfv[CH], qbv[CH];
#pragma unroll
        for (int j = 0; j < CH; j++) {
            int i = base + j;
            float bv = sb[pidx(i)];
            float pf, sv;
            if (h == 0) {
                pf = (i >= 14) ? sp[pidx(i - 14)] : 1.0f;
                sv = (i <= 4082) ? (C2 - sp[pidx(i + 13)]) : (C2 - stripA[i - 4083]);
            } else {
                pf = (i >= 14) ? sp[pidx(i - 14)] : stripA[i + 75];
                sv = (i < 4082) ? (C2 - sp[pidx(i + 13)]) : 1.0f;
            }
            qfv[j] = bv * pf;
            qbv[j] = bv * sv;
        }
#pragma unroll
        for (int j = 1; j < CH; j++) { qfv[j] += qfv[j - 1]; qbv[j] += qbv[j - 1]; }
        float tf = qfv[CH - 1], tb = qbv[CH - 1];
        float xf = tf, xb = tb;
#pragma unroll
        for (int d = 1; d < 32; d <<= 1) {
            float yf = __shfl_up_sync(0xFFFFFFFFu, xf, d);
            float yb = __shfl_up_sync(0xFFFFFFFFu, xb, d);
            if (lane >= d) { xf += yf; xb += yb; }
        }
        if (lane == 31) { wredf[wid] = xf; wredb[wid] = xb; }
        __syncthreads();
        if (wid == 0) {
            float wf = (lane < NW) ? wredf[lane] : 0.0f;
            float wb = (lane < NW) ? wredb[lane] : 0.0f;
#pragma unroll
            for (int d = 1; d < 32; d <<= 1) {
                float yf = __shfl_up_sync(0xFFFFFFFFu, wf, d);
                float yb = __shfl_up_sync(0xFFFFFFFFu, wb, d);
                if (lane >= d) { wf += yf; wb += yb; }
            }
            if (lane < NW) { wredf[lane] = wf; wredb[lane] = wb; }
        }
        __syncthreads();
        float offf = (xf - tf) + (wid > 0 ? wredf[wid - 1] : 0.0f);
        float offb = (xb - tb) + (wid > 0 ? wredb[wid - 1] : 0.0f);
#pragma unroll
        for (int j = 0; j < CH; j++) {
            qf[pidx(base + j)] = offf + qfv[j];   // LOCAL inclusive prefix
            qb[pidx(base + j)] = offb + qbv[j];
        }
    }
    __syncthreads();

    // ---- D: all 9 channels, barrier-free; input re-gathered (L2-hot) ----
    const float kI = k * invZ1;
#pragma unroll
    for (int ii = 0; ii < CH; ii++) {
        int tl = ii * NT + tid;
        int tg = hb + tl;
        const float4* p4 = reinterpret_cast<const float4*>(gin) + ((9 * tg) >> 2);
        float4 q0 = p4[0], q1 = p4[1], q2 = p4[2];
        float w12[12] = { q0.x, q0.y, q0.z, q0.w,
                          q1.x, q1.y, q1.z, q1.w,
                          q2.x, q2.y, q2.z, q2.w };
        float v[9];
#pragma unroll
        for (int c = 0; c < 9; c++) v[c] = sel4(rw, w12[c], w12[c + 1], w12[c + 2], w12[c + 3]);

        float bv = v[0];
        float wfv, wbv;
        if (h == 0) {
            wfv = ((tl >= 16) ? qf[pidx(tl - 16)] : 0.0f)
                - ((tl >= 76) ? qf[pidx(tl - 76)] : 0.0f);
            if (tl >= 4021) {
                float own = (tl <= 4079) ? (qb[pidx(HALF - 1)] - qb[pidx(tl + 15)]) : 0.0f;
                float st  = stripB[tl - 4020] - ((tl >= 4080) ? stripB[tl - 4080] : 0.0f);
                wbv = own + st;
            } else {
                wbv = qb[pidx(tl + 75)] - qb[pidx(tl + 15)];
            }
        } else {
            if (tl < 76) {
                wfv = (tl < 16) ? (stripB[tl] - stripB[tl + 60])
                                : (stripB[tl] + qf[pidx(tl - 16)]);
            } else {
                wfv = qf[pidx(tl - 16)] - qf[pidx(tl - 76)];
            }
            int hi = tl + 75; if (hi > HALF - 1) hi = HALF - 1;
            int lo = tl + 15; if (lo > HALF - 1) lo = HALF - 1;
            wbv = qb[pidx(hi)] - qb[pidx(lo)];
        }
        float w = wfv + wbv;
        float o = fmaf(bv * kI, w, bv * invZ1);     // b > eps fast path
        if (!(bv > 1e-13f)) {
            float t0 = fmaf(k, w, 1.0f);
            o = (bv * bv * t0) / (bv + 1.0f) * invZ1;
        }
        outb[tg] = clip01(o);

#pragma unroll
        for (int c = 1; c < 9; c++) {
            float vv = v[c];
            float u = (vv > 1e-13f) ? vv : (vv * vv) / (vv + 1.0f);
            outb[(size_t)c * L + tg] = clip01(u * invZ1);
        }
    }
}

extern "C" void kernel_launch(void* const* d_in, const int* in_sizes, int n_in,
                              void* d_out, int out_size) {
    const float* conc = (const float*)d_in[0];
    const float* kern = (const float*)d_in[1];
    float* out = (float*)d_out;
    const int B = in_sizes[0] / (L * F);

    const size_t smem = (size_t)4 * PLH * sizeof(float);   // 73,728 B -> 2 CTAs/SM
    cudaFuncSetAttribute(kenneth_kernel,
                         cudaFuncAttributeMaxDynamicSharedMemorySize, (int)smem);
    kenneth_kernel<<<2 * B, NT, smem>>>(conc, kern, out);
}

// round 14
// speedup vs baseline: 1.8577x; 1.8577x over previous
#include <cuda_runtime.h>
#include <cstdint>

#define L      8192
#define F      9
#define NT     1024
#define CH     8                 // tiles (rows per thread)
#define PL     9216              // padded scan length: L + L/8  (== TFLOAT)
#define TFLOAT 9216              // floats per tile = NT * F
#define TBYTES 36864             // bytes per tile

__device__ __forceinline__ int pidx(int t) { return t + (t >> 3); }
__device__ __forceinline__ float clip01(float x) { return fminf(fmaxf(x, 0.0f), 0.9999f); }

__device__ __forceinline__ uint32_t smem_u32(const void* p) {
    uint32_t a;
    asm("{ .reg .u64 t; cvta.to.shared.u64 t, %1; cvt.u32.u64 %0, t; }" : "=r"(a) : "l"(p));
    return a;
}
__device__ __forceinline__ void mbar_init(uint32_t mbar, uint32_t cnt) {
    asm volatile("mbarrier.init.shared.b64 [%0], %1;" :: "r"(mbar), "r"(cnt) : "memory");
}
__device__ __forceinline__ void mbar_expect_tx(uint32_t mbar, uint32_t bytes) {
    asm volatile("mbarrier.arrive.expect_tx.shared.b64 _, [%0], %1;" :: "r"(mbar), "r"(bytes) : "memory");
}
__device__ __forceinline__ void bulk_g2s(uint32_t dst, const float* src, uint32_t bytes, uint32_t mbar) {
    asm volatile("cp.async.bulk.shared::cta.global.mbarrier::complete_tx::bytes [%0], [%1], %2, [%3];"
                 :: "r"(dst), "l"(src), "r"(bytes), "r"(mbar) : "memory");
}
__device__ __forceinline__ void mbar_wait_acq(uint32_t mbar, uint32_t parity) {
    asm volatile(
        "{\n\t.reg .pred P;\n\t"
        "W_%=:\n\t"
        "mbarrier.try_wait.parity.acquire.cta.shared::cta.b64 P, [%0], %1, 0x989680;\n\t"
        "@P bra.uni D_%=;\n\t"
        "bra.uni W_%=;\n\t"
        "D_%=:\n\t}"
        :: "r"(mbar), "r"(parity) : "memory");
}

__global__ __launch_bounds__(NT, 1)
void kenneth_kernel(const float* __restrict__ conc,
                    const float* __restrict__ kern,
                    float* __restrict__ out) {
    extern __shared__ float sm[];
    float* sb = sm;            // bcd (padded)
    float* sp = sm + PL;       // rowsum -> P (padded)
    float* qf = sm + 2 * PL;   // stage buf 0 / Q_f
    float* qb = sm + 3 * PL;   // stage buf 1 / Q_b
    __shared__ float wredp[32], wredf[32], wredb[32];
    __shared__ float sZ1;
    __shared__ uint64_t mbar_s[2];

    const int tid  = threadIdx.x;
    const int lane = tid & 31;
    const int wid  = tid >> 5;
    const float k  = kern[0];
    const float* gin = conc + (size_t)blockIdx.x * (L * F);
    float* outb = out + (size_t)blockIdx.x * (F * L);

    const uint32_t mb0 = smem_u32(&mbar_s[0]);
    const uint32_t mb1 = smem_u32(&mbar_s[1]);
    const uint32_t stg0 = smem_u32(qf);
    const uint32_t stg1 = smem_u32(qb);

    // ---- Init mbarriers + first two tile DMAs ----
    if (tid == 0) {
        mbar_init(mb0, 1);
        mbar_init(mb1, 1);
        sZ1 = 1.0f;
    }
    __syncthreads();
    if (tid == 0) {
        mbar_expect_tx(mb0, TBYTES);
        bulk_g2s(stg0, gin, TBYTES, mb0);
        mbar_expect_tx(mb1, TBYTES);
        bulk_g2s(stg1, gin + TFLOAT, TBYTES, mb1);
    }

    // ---- Phase Z: Z1 = 1 + sum(all inputs); overlaps in-flight DMAs ----
    {
        const float4* g4 = reinterpret_cast<const float4*>(gin);
        float tot = 0.0f;
#pragma unroll
        for (int g = 0; g < 18; g++) {
            float4 q = g4[g * NT + tid];
            tot += (q.x + q.y) + (q.z + q.w);
        }
#pragma unroll
        for (int d = 16; d >= 1; d >>= 1) tot += __shfl_xor_sync(0xFFFFFFFFu, tot, d);
        if (lane == 0) atomicAdd(&sZ1, tot);   // 32 lane-0 adds, single barrier
        __syncthreads();
    }
    const float Z1 = sZ1;
    const float C2 = Z1 + 1.0f;
    const float invZ1 = 1.0f / Z1;

    // ---- Phase A: 2-buffer pipelined tiles; final ch1..8 stores here ----
    float bcd[CH];
#pragma unroll
    for (int ii = 0; ii < CH; ii++) {
        float* stgb = (ii & 1) ? qb : qf;
        mbar_wait_acq((ii & 1) ? mb1 : mb0, (ii >> 1) & 1);

        float v[9];
#pragma unroll
        for (int c = 0; c < 9; c++) v[c] = stgb[9 * tid + c];

        if (ii + 2 < CH) {               // a refill follows: prove buffer consumed
            __syncthreads();
            if (tid == 0) {
                uint32_t mb = (ii & 1) ? mb1 : mb0;
                mbar_expect_tx(mb, TBYTES);
                bulk_g2s((ii & 1) ? stg1 : stg0, gin + (ii + 2) * TFLOAT, TBYTES, mb);
            }
        }

        int t = ii * NT + tid;
        float bv = v[0];
        float acc = ((v[1] + v[2]) + (v[3] + v[4]))
                  + ((v[5] + v[6]) + (v[7] + v[8])) + v[0];
        bcd[ii] = bv;
        sb[pidx(t)] = bv;
        sp[pidx(t)] = acc;

#pragma unroll
        for (int c = 1; c < 9; c++) {
            float vv = v[c];
            float u = (vv > 1e-13f) ? vv : (vv * vv) / (vv + 1.0f);
            outb[(size_t)c * L + t] = clip01(u * invZ1);
        }
    }
    __syncthreads();

    // ---- Phase B: P = 1 + inclusive cumsum(rowsum), chunked ownership ----
    const int base = CH * tid;
    {
        float pv[CH];
        float run = 0.0f;
#pragma unroll
        for (int j = 0; j < CH; j++) { run += sp[pidx(base + j)]; pv[j] = run; }
        float x = run;
#pragma unroll
        for (int d = 1; d < 32; d <<= 1) {
            float y = __shfl_up_sync(0xFFFFFFFFu, x, d);
            if (lane >= d) x += y;
        }
        if (lane == 31) wredp[wid] = x;
        __syncthreads();
        if (wid == 0) {
            float w = wredp[lane];
#pragma unroll
            for (int d = 1; d < 32; d <<= 1) {
                float y = __shfl_up_sync(0xFFFFFFFFu, w, d);
                if (lane >= d) w += y;
            }
            wredp[lane] = w;
        }
        __syncthreads();
        float off = 1.0f + (x - run) + (wid > 0 ? wredp[wid - 1] : 0.0f);
#pragma unroll
        for (int j = 0; j < CH; j++) sp[pidx(base + j)] = off + pv[j];
    }
    __syncthreads();

    // ---- Phase C: build q_f/q_b and fused dual scan (overwrites stage bufs) ----
    {
        float qfv[CH], qbv[CH];
#pragma unroll
        for (int j = 0; j < CH; j++) {
            int i = base + j;
            float bv = sb[pidx(i)];
            float pf = (i >= 14)    ? sp[pidx(i - 14)]        : 1.0f;
            float sv = (i + 14 < L) ? (C2 - sp[pidx(i + 13)]) : 1.0f;
            qfv[j] = bv * pf;
            qbv[j] = bv * sv;
        }
#pragma unroll
        for (int j = 1; j < CH; j++) { qfv[j] += qfv[j - 1]; qbv[j] += qbv[j - 1]; }
        float tf = qfv[CH - 1], tb = qbv[CH - 1];
        float xf = tf, xb = tb;
#pragma unroll
        for (int d = 1; d < 32; d <<= 1) {
            float yf = __shfl_up_sync(0xFFFFFFFFu, xf, d);
            float yb = __shfl_up_sync(0xFFFFFFFFu, xb, d);
            if (lane >= d) { xf += yf; xb += yb; }
        }
        if (lane == 31) { wredf[wid] = xf; wredb[wid] = xb; }
        __syncthreads();
        if (wid == 0) {
            float wf = wredf[lane], wb = wredb[lane];
#pragma unroll
            for (int d = 1; d < 32; d <<= 1) {
                float yf = __shfl_up_sync(0xFFFFFFFFu, wf, d);
                float yb = __shfl_up_sync(0xFFFFFFFFu, wb, d);
                if (lane >= d) { wf += yf; wb += yb; }
            }
            wredf[lane] = wf; wredb[lane] = wb;
        }
        __syncthreads();
        float offf = (xf - tf) + (wid > 0 ? wredf[wid - 1] : 0.0f);
        float offb = (xb - tb) + (wid > 0 ? wredb[wid - 1] : 0.0f);
#pragma unroll
        for (int j = 0; j < CH; j++) {
            qf[pidx(base + j)] = offf + qfv[j];
            qb[pidx(base + j)] = offb + qbv[j];
        }
    }
    __syncthreads();

    // ---- Phase D: channel 0 (windows), strided, coalesced, division-free ----
    const float kI = k * invZ1;
    const float qbLast = qb[pidx(L - 1)];
#pragma unroll
    for (int ii = 0; ii < CH; ii++) {
        int t = ii * NT + tid;
        float bv = bcd[ii];
        float wfv = ((t >= 16) ? qf[pidx(t - 16)] : 0.0f)
                  - ((t >= 76) ? qf[pidx(t - 76)] : 0.0f);
        float wbv;
        if (t + 75 <= L - 1) {
            wbv = qb[pidx(t + 75)] - qb[pidx(t + 15)];
        } else {
            wbv = qbLast - ((t + 15 <= L - 1) ? qb[pidx(t + 15)] : qbLast);
        }
        float w = wfv + wbv;
        float o = fmaf(bv * kI, w, bv * invZ1);      // b > eps fast path
        if (!(bv > 1e-13f)) {
            float t0 = fmaf(k, w, 1.0f);
            o = (bv * bv * t0) / (bv + 1.0f) * invZ1;
        }
        outb[t] = clip01(o);
    }
}

extern "C" void kernel_launch(void* const* d_in, const int* in_sizes, int n_in,
                              void* d_out, int out_size) {
    const float* conc = (const float*)d_in[0];
    const float* kern = (const float*)d_in[1];
    float* out = (float*)d_out;
    const int B = in_sizes[0] / (L * F);

    const size_t smem = (size_t)4 * PL * sizeof(float);  // 147,456 B
    cudaFuncSetAttribute(kenneth_kernel,
                         cudaFuncAttributeMaxDynamicSharedMemorySize, (int)smem);
    kenneth_kernel<<<B, NT, smem>>>(conc, kern, out);
}